// round 13
// baseline (speedup 1.0000x reference)
#include <cuda_runtime.h>
#include <cuda_fp16.h>
#include <cstdint>

#define BB 32
#define CC 64
#define HH 64
#define WW 64
#define EE 8
#define HWC (HH*WW)

// Scratch (device globals: no allocation allowed)
__device__ float          g_S[BB * 9 * CC];   // box sums [(b*9+k)*64+c]
__device__ int            g_cnt[BB];
__device__ volatile int   g_flag[BB];
__device__ volatile float g_val[BB];
__device__ volatile int   g_idx[BB];

// ===========================================================================
// helpers
// ===========================================================================
__device__ __forceinline__ uint32_t smem_u32(const void* p) {
    uint32_t a;
    asm("{ .reg .u64 t; cvta.to.shared.u64 t, %1; cvt.u32.u64 %0, t; }" : "=r"(a) : "l"(p));
    return a;
}

__device__ __forceinline__ uint32_t pack_f16x2(float even, float odd) {
    __half2 h = __floats2half2_rn(even, odd);
    return *reinterpret_cast<uint32_t*>(&h);
}

#define LDMATRIX_X2T(R, addr) \
    asm volatile("ldmatrix.sync.aligned.m8n8.x2.trans.shared.b16 {%0,%1}, [%2];" \
        : "=r"((R)[0]), "=r"((R)[1]) : "r"(addr))

#define MMA_F16(D, A, B0, B1) \
    asm volatile("mma.sync.aligned.m16n8k16.row.col.f32.f16.f16.f32 " \
        "{%0,%1,%2,%3}, {%4,%5,%6,%7}, {%8,%9}, {%0,%1,%2,%3};" \
        : "+f"((D)[0]), "+f"((D)[1]), "+f"((D)[2]), "+f"((D)[3]) \
        : "r"((A)[0]), "r"((A)[1]), "r"((A)[2]), "r"((A)[3]), "r"(B0), "r"(B1))

// ===========================================================================
// Kernel 0: reset counters/flags
// ===========================================================================
__global__ void zero_kernel() {
    int i = threadIdx.x;
    if (i < BB) { g_cnt[i] = 0; g_flag[i] = 0; }
}

// ===========================================================================
// Pipe kernel, interleaved roles (lag = 8 batches).
// bid layout: [A(b=0..7) : 256] [24 groups of (A(b=g+8):32, B(b=g):32)] [B(24..31) : 256]
//  A-role: region stats for 2 channels (reads x; x lands in L2 for B).
//          Last A-block of batch computes gate inline, sets flag[b].
//  B-role: spin flag[b] (A(b) retired ~1 wave earlier), read x fp32 (L2-hot),
//          convert fp16, stage smem, mma.sync GEMM, streaming stores.
// Every wave carries both roles -> read & write streams overlap.
// ===========================================================================
#define XPITCH 68u   // words per X row (64 data words + 4 pad)

__global__ __launch_bounds__(256) void pipe_kernel(const float* __restrict__ x,
                                                   const float* __restrict__ expert_w,
                                                   const float* __restrict__ gate_w,
                                                   const float* __restrict__ gate_b,
                                                   float* __restrict__ out,
                                                   int write_ew) {
    __shared__ uint32_t sX[64 * XPITCH];     // B-role tile (A-role unused)
    __shared__ float sRow[2][4][16];
    __shared__ float sRE[2][4][4];
    __shared__ float sCol[2][4][16];
    __shared__ float sG[2][8];
    __shared__ float Ssh[9 * 64];
    __shared__ float gat[8];
    __shared__ float shv;
    __shared__ int   she, shLast;

    const int tid  = threadIdx.x;
    const int warp = tid >> 5, lane = tid & 31;
    const int bid  = blockIdx.x;

    // ---- role decode (lag-8 interleave) ----
    int role, b, idx;
    if (bid < 256) {
        role = 0; b = bid >> 5; idx = bid & 31;
    } else if (bid < 1792) {
        int j = bid - 256, grp = j >> 6, r = j & 63;
        if (r < 32) { role = 0; b = grp + 8; idx = r; }
        else        { role = 1; b = grp;     idx = r - 32; }
    } else {
        role = 1; b = 24 + ((bid - 1792) >> 5); idx = bid & 31;
    }

    if (role == 0) {
        // ================= A-role: region stats for channels 2*idx, 2*idx+1 ====
        const int c0 = idx * 2;
        const float4* base0 = (const float4*)(x + ((size_t)b * CC + c0) * HWC);
        const float4* base1 = (const float4*)(x + ((size_t)b * CC + c0 + 1) * HWC);
        float4 va[4], vb4[4];
        #pragma unroll
        for (int i = 0; i < 4; i++) va[i]  = base0[i * 256 + tid];
        #pragma unroll
        for (int i = 0; i < 4; i++) vb4[i] = base1[i * 256 + tid];

        const int g  = tid >> 4;
        const int c4 = tid & 15;

        #pragma unroll
        for (int m = 0; m < 2; m++) {
            const float4* v = m ? vb4 : va;
            float ps[4], gsum = 0.f;
            #pragma unroll
            for (int i = 0; i < 4; i++) {
                ps[i] = (v[i].x + v[i].y) + (v[i].z + v[i].w);
                gsum += ps[i];
            }
            if (g == 0)  sRow[m][0][c4] = ps[0];
            if (g == 1)  sRow[m][1][c4] = ps[0];
            if (g == 14) sRow[m][2][c4] = ps[3];
            if (g == 15) sRow[m][3][c4] = ps[3];
            if (c4 == 0) {
                sCol[m][0][g] = (v[0].x + v[1].x) + (v[2].x + v[3].x);
                sCol[m][1][g] = (v[0].y + v[1].y) + (v[2].y + v[3].y);
                if (g == 0)  { sRE[m][0][0] = v[0].x; sRE[m][0][1] = v[0].y; }
                if (g == 1)  { sRE[m][1][0] = v[0].x; sRE[m][1][1] = v[0].y; }
                if (g == 14) { sRE[m][2][0] = v[3].x; sRE[m][2][1] = v[3].y; }
                if (g == 15) { sRE[m][3][0] = v[3].x; sRE[m][3][1] = v[3].y; }
            }
            if (c4 == 15) {
                sCol[m][2][g] = (v[0].z + v[1].z) + (v[2].z + v[3].z);
                sCol[m][3][g] = (v[0].w + v[1].w) + (v[2].w + v[3].w);
                if (g == 0)  { sRE[m][0][2] = v[0].z; sRE[m][0][3] = v[0].w; }
                if (g == 1)  { sRE[m][1][2] = v[0].z; sRE[m][1][3] = v[0].w; }
                if (g == 14) { sRE[m][2][2] = v[3].z; sRE[m][2][3] = v[3].w; }
                if (g == 15) { sRE[m][3][2] = v[3].z; sRE[m][3][3] = v[3].w; }
            }
            #pragma unroll
            for (int o = 16; o; o >>= 1) gsum += __shfl_xor_sync(0xffffffffu, gsum, o);
            if (lane == 0) sG[m][warp] = gsum;
        }
        __syncthreads();

        if (tid < 18) {
            int m = tid / 9, k = tid - m * 9;
            int di = k / 3, dj = k - di * 3;
            float G = 0.f;
            #pragma unroll
            for (int j = 0; j < 8; j++) G += sG[m][j];
            float cc0 = 0.f, cc1 = 0.f, cc62 = 0.f, cc63 = 0.f;
            #pragma unroll
            for (int j = 0; j < 16; j++) {
                cc0 += sCol[m][0][j]; cc1 += sCol[m][1][j];
                cc62 += sCol[m][2][j]; cc63 += sCol[m][3][j];
            }
            float colc = (dj == 0) ? (cc62 + cc63) : (dj == 1) ? (cc0 + cc63) : (cc0 + cc1);
            float T = G - colc;
            float rw[4];
            #pragma unroll
            for (int er = 0; er < 4; er++) {
                float s = 0.f;
                #pragma unroll
                for (int j = 0; j < 16; j++) s += sRow[m][er][j];
                float ec = (dj == 0) ? (sRE[m][er][2] + sRE[m][er][3])
                         : (dj == 1) ? (sRE[m][er][0] + sRE[m][er][3])
                                     : (sRE[m][er][0] + sRE[m][er][1]);
                rw[er] = s - ec;
            }
            float sub = (di == 0) ? (rw[2] + rw[3])
                      : (di == 1) ? (rw[0] + rw[3])
                                  : (rw[0] + rw[1]);
            g_S[(b * 9 + k) * CC + (c0 + m)] = T - sub;
        }
        __syncthreads();

        if (tid == 0) {
            __threadfence();
            int old = atomicAdd(&g_cnt[b], 1);
            shLast = (old == 31);
        }
        __syncthreads();
        if (!shLast) return;

        // ---- gate (last A-block of this batch) ----
        __threadfence();
        for (int i = tid; i < 576; i += 256) Ssh[i] = g_S[b * 576 + i];
        __syncthreads();
        float acc = 0.f;
        for (int idx2 = lane; idx2 < 576; idx2 += 32) {
            int c = idx2 / 9;
            int k = idx2 - c * 9;
            acc += gate_w[warp * 576 + idx2] * Ssh[k * 64 + c];
        }
        #pragma unroll
        for (int o = 16; o; o >>= 1) acc += __shfl_down_sync(0xffffffffu, acc, o);
        if (lane == 0) gat[warp] = acc + gate_b[warp] * 3844.0f;
        __syncthreads();
        if (tid == 0) {
            float mm = gat[0]; int mi = 0;
            #pragma unroll
            for (int e2 = 1; e2 < 8; e2++) { if (gat[e2] > mm) { mm = gat[e2]; mi = e2; } }
            float s = 0.f;
            #pragma unroll
            for (int e2 = 0; e2 < 8; e2++) s += expf(gat[e2] - mm);
            float v_ = 1.0f / s;
            g_val[b] = v_;
            g_idx[b] = mi;
            if (write_ew) {
                float* ew = out + BB * CC * HWC + b * 8;
                #pragma unroll
                for (int e2 = 0; e2 < 8; e2++) ew[e2] = (e2 == mi) ? v_ : 0.0f;
            }
            __threadfence();
            g_flag[b] = 1;
        }
        return;
    }

    // ================= B-role: GEMM for (b, chunk=idx) =================
    const int hw0 = idx * 128;

    if (tid == 0) {
        while (g_flag[b] == 0) __nanosleep(128);
        __threadfence();
        shv = g_val[b];
        she = g_idx[b];
    }

    // ---- stage x (fp32, L2-hot from A's pass) -> fp16 smem ----
    const float* Xsrc = x + (size_t)b * CC * HWC + hw0;
    float4 xv[8];
    #pragma unroll
    for (int i = 0; i < 8; i++) {
        int p = tid + i * 256;              // float4 index 0..2047
        int c = p >> 5, q = p & 31;         // 32 float4 per 128-float row
        xv[i] = *(const float4*)(Xsrc + (size_t)c * HWC + q * 4);
    }
    #pragma unroll
    for (int i = 0; i < 8; i++) {
        int p = tid + i * 256;
        int c = p >> 5, q = p & 31;
        uint2 w;
        w.x = pack_f16x2(xv[i].x, xv[i].y);
        w.y = pack_f16x2(xv[i].z, xv[i].w);
        *(uint2*)(sX + c * XPITCH + q * 2) = w;
    }
    __syncthreads();
    const float val = shv;
    const int   e   = she;

    // ---- A fragments (fp16 W) from L2-hot gmem ----
    const int wf = warp >> 1;   // 0..3 : 16 f rows each
    const int wn = warp & 1;    // 0..1 : 64 hw cols each
    uint32_t af[4][4];
    {
        const float* Wb = expert_w + (size_t)e * 4096;
        int r0 = wf * 16 + (lane >> 2);
        int kA = (lane & 3) * 2;
        #pragma unroll
        for (int kt = 0; kt < 4; kt++) {
            int k0 = kt * 16 + kA;
            float2 w0 = *(const float2*)(Wb + r0 * 64 + k0);
            float2 w1 = *(const float2*)(Wb + (r0 + 8) * 64 + k0);
            float2 w2 = *(const float2*)(Wb + r0 * 64 + k0 + 8);
            float2 w3 = *(const float2*)(Wb + (r0 + 8) * 64 + k0 + 8);
            af[kt][0] = pack_f16x2(w0.x, w0.y);
            af[kt][1] = pack_f16x2(w1.x, w1.y);
            af[kt][2] = pack_f16x2(w2.x, w2.y);
            af[kt][3] = pack_f16x2(w3.x, w3.y);
        }
    }

    float acc2[8][4];
    #pragma unroll
    for (int nt = 0; nt < 8; nt++)
        #pragma unroll
        for (int qv = 0; qv < 4; qv++) acc2[nt][qv] = 0.f;

    const uint32_t sxb = smem_u32(sX);
    const uint32_t krow = (uint32_t)(lane & 15);
    #pragma unroll
    for (int kt = 0; kt < 4; kt++) {
        uint32_t kbase = ((uint32_t)(kt * 16) + krow) * (XPITCH * 4u);
        #pragma unroll
        for (int nt = 0; nt < 8; nt++) {
            uint32_t noff = (uint32_t)(wn * 64 + nt * 8) * 2u;
            uint32_t bf[2];
            LDMATRIX_X2T(bf, sxb + kbase + noff);
            MMA_F16(acc2[nt], af[kt], bf[0], bf[1]);
        }
    }

    // ---- epilogue: streaming stores ----
    float* outb = out + (size_t)b * CC * HWC + hw0;
    int f0 = wf * 16 + (lane >> 2);
    int cbase = wn * 64 + (lane & 3) * 2;
    #pragma unroll
    for (int nt = 0; nt < 8; nt++) {
        int cc = cbase + nt * 8;
        float2 v0 = make_float2(acc2[nt][0] * val, acc2[nt][1] * val);
        float2 v1 = make_float2(acc2[nt][2] * val, acc2[nt][3] * val);
        __stcs((float2*)(outb + (size_t)f0 * HWC + cc),       v0);
        __stcs((float2*)(outb + (size_t)(f0 + 8) * HWC + cc), v1);
    }
}

// ===========================================================================
extern "C" void kernel_launch(void* const* d_in, const int* in_sizes, int n_in,
                              void* d_out, int out_size) {
    const float* x = nullptr, *gate_w = nullptr, *gate_b = nullptr, *expert_w = nullptr;
    for (int i = 0; i < n_in; i++) {
        switch (in_sizes[i]) {
            case BB*CC*HH*WW: x        = (const float*)d_in[i]; break;  // 524288
            case EE*CC*3*3:   gate_w   = (const float*)d_in[i]; break;  // 4608
            case EE:          gate_b   = (const float*)d_in[i]; break;  // 8
            case EE*CC*CC:    expert_w = (const float*)d_in[i]; break;  // 32768
            default: break;
        }
    }
    float* out = (float*)d_out;
    const int main_elems = BB * CC * HWC;
    int write_ew = (out_size >= main_elems + BB * EE) ? 1 : 0;

    zero_kernel<<<1, 32>>>();
    pipe_kernel<<<2048, 256>>>(x, expert_w, gate_w, gate_b, out, write_ew);
}

// round 14
// speedup vs baseline: 1.2197x; 1.2197x over previous
#include <cuda_runtime.h>
#include <cuda_fp16.h>
#include <cstdint>

#define BB 32
#define CC 64
#define HH 64
#define WW 64
#define EE 8
#define HWC (HH*WW)

// Scratch (device globals: no allocation allowed)
__device__ float g_S[BB * 9 * CC];   // box sums [(b*9+k)*64+c], k=di*3+dj
__device__ float g_val[BB];
__device__ int   g_idx[BB];

// ===========================================================================
// helpers
// ===========================================================================
__device__ __forceinline__ uint32_t smem_u32(const void* p) {
    uint32_t a;
    asm("{ .reg .u64 t; cvta.to.shared.u64 t, %1; cvt.u32.u64 %0, t; }" : "=r"(a) : "l"(p));
    return a;
}

__device__ __forceinline__ uint32_t pack_f16x2(float even, float odd) {
    __half2 h = __floats2half2_rn(even, odd);
    return *reinterpret_cast<uint32_t*>(&h);
}

#define LDMATRIX_X2T(R, addr) \
    asm volatile("ldmatrix.sync.aligned.m8n8.x2.trans.shared.b16 {%0,%1}, [%2];" \
        : "=r"((R)[0]), "=r"((R)[1]) : "r"(addr))

#define MMA_F16(D, A, B0, B1) \
    asm volatile("mma.sync.aligned.m16n8k16.row.col.f32.f16.f16.f32 " \
        "{%0,%1,%2,%3}, {%4,%5,%6,%7}, {%8,%9}, {%0,%1,%2,%3};" \
        : "+f"((D)[0]), "+f"((D)[1]), "+f"((D)[2]), "+f"((D)[3]) \
        : "r"((A)[0]), "r"((A)[1]), "r"((A)[2]), "r"((A)[3]), "r"(B0), "r"(B1))

// ===========================================================================
// Kernel 1: box sums (proven R6/R11 shape, convert removed).
// Block = one (b,c) image; 256 threads; float4 at i*256+tid (coalesced).
// ===========================================================================
__global__ __launch_bounds__(256) void region_sums_kernel(const float* __restrict__ x) {
    const int tid = threadIdx.x;
    const float4* base = (const float4*)(x + (size_t)blockIdx.x * HWC);
    float4 v[4];
    #pragma unroll
    for (int i = 0; i < 4; i++) v[i] = base[i * 256 + tid];

    const int g  = tid >> 4;   // 0..15 ; rows touched = i*16 + g
    const int c4 = tid & 15;   // float4 within row

    __shared__ float sRow[4][16];  // partial sums of edge rows 0,1,62,63
    __shared__ float sRE[4][4];    // edge row elems: x[r][0],[1],[62],[63]
    __shared__ float sCol[4][16];  // per-g partials of cols 0,1,62,63
    __shared__ float sG[8];        // per-warp grand totals

    float ps[4], gsum = 0.f;
    #pragma unroll
    for (int i = 0; i < 4; i++) {
        ps[i] = (v[i].x + v[i].y) + (v[i].z + v[i].w);
        gsum += ps[i];
    }
    // edge rows: 0=(i0,g0), 1=(i0,g1), 62=(i3,g14), 63=(i3,g15)
    if (g == 0)  sRow[0][c4] = ps[0];
    if (g == 1)  sRow[1][c4] = ps[0];
    if (g == 14) sRow[2][c4] = ps[3];
    if (g == 15) sRow[3][c4] = ps[3];
    if (c4 == 0) {
        sCol[0][g] = (v[0].x + v[1].x) + (v[2].x + v[3].x);
        sCol[1][g] = (v[0].y + v[1].y) + (v[2].y + v[3].y);
        if (g == 0)  { sRE[0][0] = v[0].x; sRE[0][1] = v[0].y; }
        if (g == 1)  { sRE[1][0] = v[0].x; sRE[1][1] = v[0].y; }
        if (g == 14) { sRE[2][0] = v[3].x; sRE[2][1] = v[3].y; }
        if (g == 15) { sRE[3][0] = v[3].x; sRE[3][1] = v[3].y; }
    }
    if (c4 == 15) {
        sCol[2][g] = (v[0].z + v[1].z) + (v[2].z + v[3].z);
        sCol[3][g] = (v[0].w + v[1].w) + (v[2].w + v[3].w);
        if (g == 0)  { sRE[0][2] = v[0].z; sRE[0][3] = v[0].w; }
        if (g == 1)  { sRE[1][2] = v[0].z; sRE[1][3] = v[0].w; }
        if (g == 14) { sRE[2][2] = v[3].z; sRE[2][3] = v[3].w; }
        if (g == 15) { sRE[3][2] = v[3].z; sRE[3][3] = v[3].w; }
    }
    #pragma unroll
    for (int o = 16; o; o >>= 1) gsum += __shfl_xor_sync(0xffffffffu, gsum, o);
    if ((tid & 31) == 0) sG[tid >> 5] = gsum;
    __syncthreads();

    if (tid < 9) {
        int di = tid / 3, dj = tid - di * 3;
        float G = 0.f;
        #pragma unroll
        for (int j = 0; j < 8; j++) G += sG[j];
        float c0 = 0.f, c1 = 0.f, c62 = 0.f, c63 = 0.f;
        #pragma unroll
        for (int j = 0; j < 16; j++) {
            c0 += sCol[0][j]; c1 += sCol[1][j]; c62 += sCol[2][j]; c63 += sCol[3][j];
        }
        float colc = (dj == 0) ? (c62 + c63) : (dj == 1) ? (c0 + c63) : (c0 + c1);
        float T = G - colc;                 // sum of cv_dj over all 64 rows
        float rw[4];
        #pragma unroll
        for (int er = 0; er < 4; er++) {
            float s = 0.f;
            #pragma unroll
            for (int j = 0; j < 16; j++) s += sRow[er][j];
            float ec = (dj == 0) ? (sRE[er][2] + sRE[er][3])
                     : (dj == 1) ? (sRE[er][0] + sRE[er][3])
                                 : (sRE[er][0] + sRE[er][1]);
            rw[er] = s - ec;                // cv_dj of that edge row
        }
        float sub = (di == 0) ? (rw[2] + rw[3])
                  : (di == 1) ? (rw[0] + rw[3])
                              : (rw[0] + rw[1]);
        int b = blockIdx.x >> 6, c = blockIdx.x & 63;
        g_S[(b * 9 + tid) * CC + c] = T - sub;
    }
}

// ===========================================================================
// Kernel 2: gate (32 blocks; smem-staged g_S).
// ===========================================================================
__global__ __launch_bounds__(256) void gate_kernel(const float* __restrict__ gate_w,
                                                   const float* __restrict__ gate_b,
                                                   float* __restrict__ ew_out,
                                                   int write_ew) {
    int b = blockIdx.x;
    int tid = threadIdx.x;
    __shared__ float Ssh[9 * 64];
    __shared__ float gat[8];

    for (int i = tid; i < 576; i += 256) Ssh[i] = g_S[b*576 + i];
    __syncthreads();

    int warp = tid >> 5, lane = tid & 31;  // warp = expert
    float acc = 0.f;
    for (int idx = lane; idx < 576; idx += 32) {
        int c = idx / 9;
        int k = idx - c * 9;
        acc += gate_w[warp * 576 + idx] * Ssh[k * 64 + c];
    }
    #pragma unroll
    for (int o = 16; o; o >>= 1) acc += __shfl_down_sync(0xffffffffu, acc, o);
    if (lane == 0) gat[warp] = acc + gate_b[warp] * 3844.0f;  // 62*62 positions
    __syncthreads();

    if (tid == 0) {
        float m = gat[0]; int mi = 0;
        #pragma unroll
        for (int e = 1; e < 8; e++) { if (gat[e] > m) { m = gat[e]; mi = e; } }
        float s = 0.f;
        #pragma unroll
        for (int e = 0; e < 8; e++) s += expf(gat[e] - m);
        g_val[b] = 1.0f / s;
        g_idx[b] = mi;
    }
    __syncthreads();
    if (write_ew && tid < 8) {
        ew_out[b * 8 + tid] = (tid == g_idx[b]) ? g_val[b] : 0.0f;
    }
}

// ===========================================================================
// Kernel 3: fp16 mma.sync GEMM, smem-staged coalesced epilogue.
//   reads x fp32 (L2-hot after kernel 1), converts fp16, 64 HMMA/warp,
//   stages the 64f x 128hw fp32 out tile in smem (rotated layout), then
//   writes full 512B-contiguous lines: 8 x STG.128 per thread.
// sBuf union: fp16 X tile (17.4KB) during mainloop, fp32 out tile (32KB) after.
// ===========================================================================
#define XPITCH 68u   // words per X row (64 data words + 4 pad)

__global__ __launch_bounds__(256) void gemm_kernel(const float* __restrict__ x,
                                                   const float* __restrict__ expert_w,
                                                   float* __restrict__ out) {
    __shared__ float sBuf[64 * 128];   // 32KB; aliased as fp16x2 tile during mainloop
    __shared__ float shv;
    __shared__ int   she;

    uint32_t* sX = (uint32_t*)sBuf;

    const int tid   = threadIdx.x;
    const int warp  = tid >> 5, lane = tid & 31;
    const int chunk = blockIdx.x;
    const int b     = blockIdx.y;
    const int hw0   = chunk * 128;

    if (tid == 0) { shv = g_val[b]; she = g_idx[b]; }

    // ---- stage x fp32 (L2-hot) -> fp16 smem ----
    const float* Xsrc = x + (size_t)b * CC * HWC + hw0;
    float4 xv[8];
    #pragma unroll
    for (int i = 0; i < 8; i++) {
        int p = tid + i * 256;              // float4 index 0..2047
        int c = p >> 5, q = p & 31;
        xv[i] = *(const float4*)(Xsrc + (size_t)c * HWC + q * 4);
    }
    #pragma unroll
    for (int i = 0; i < 8; i++) {
        int p = tid + i * 256;
        int c = p >> 5, q = p & 31;
        uint2 w;
        w.x = pack_f16x2(xv[i].x, xv[i].y);
        w.y = pack_f16x2(xv[i].z, xv[i].w);
        *(uint2*)(sX + c * XPITCH + q * 2) = w;
    }
    __syncthreads();
    const float val = shv;
    const int   e   = she;

    // ---- A fragments (fp16 W) from L2-hot gmem ----
    const int wf = warp >> 1;   // 0..3 : 16 f rows each
    const int wn = warp & 1;    // 0..1 : 64 hw cols each
    uint32_t af[4][4];
    {
        const float* Wb = expert_w + (size_t)e * 4096;
        int r0 = wf * 16 + (lane >> 2);
        int kA = (lane & 3) * 2;
        #pragma unroll
        for (int kt = 0; kt < 4; kt++) {
            int k0 = kt * 16 + kA;
            float2 w0 = *(const float2*)(Wb + r0 * 64 + k0);
            float2 w1 = *(const float2*)(Wb + (r0 + 8) * 64 + k0);
            float2 w2 = *(const float2*)(Wb + r0 * 64 + k0 + 8);
            float2 w3 = *(const float2*)(Wb + (r0 + 8) * 64 + k0 + 8);
            af[kt][0] = pack_f16x2(w0.x, w0.y);
            af[kt][1] = pack_f16x2(w1.x, w1.y);
            af[kt][2] = pack_f16x2(w2.x, w2.y);
            af[kt][3] = pack_f16x2(w3.x, w3.y);
        }
    }

    float acc[8][4];
    #pragma unroll
    for (int nt = 0; nt < 8; nt++)
        #pragma unroll
        for (int q = 0; q < 4; q++) acc[nt][q] = 0.f;

    const uint32_t sxb = smem_u32(sX);
    const uint32_t krow = (uint32_t)(lane & 15);
    #pragma unroll
    for (int kt = 0; kt < 4; kt++) {
        uint32_t kbase = ((uint32_t)(kt * 16) + krow) * (XPITCH * 4u);
        #pragma unroll
        for (int nt = 0; nt < 8; nt++) {
            uint32_t noff = (uint32_t)(wn * 64 + nt * 8) * 2u;
            uint32_t bf[2];
            LDMATRIX_X2T(bf, sxb + kbase + noff);
            MMA_F16(acc[nt], af[kt], bf[0], bf[1]);
        }
    }
    __syncthreads();   // all LDSM reads of sX done; sBuf is now the out tile

    // ---- stage out tile in smem, rotated: col' = (cc + 8*f) & 127 ----
    {
        int r0 = wf * 16 + (lane >> 2);
        int cbase = wn * 64 + (lane & 3) * 2;
        #pragma unroll
        for (int nt = 0; nt < 8; nt++) {
            int cc = cbase + nt * 8;
            int fA = r0, fB = r0 + 8;
            int cA = (cc + 8 * fA) & 127;
            int cB = (cc + 8 * fB) & 127;
            *(float2*)(sBuf + fA * 128 + cA) = make_float2(acc[nt][0] * val, acc[nt][1] * val);
            *(float2*)(sBuf + fB * 128 + cB) = make_float2(acc[nt][2] * val, acc[nt][3] * val);
        }
    }
    __syncthreads();

    // ---- coalesced output: warp writes full rows; 8 x STG.128/thread ----
    {
        float* outb = out + (size_t)b * CC * HWC + hw0;
        #pragma unroll
        for (int i = 0; i < 8; i++) {
            int f = warp + i * 8;                       // row: lanes share f
            int cs = (lane * 4 + 8 * f) & 127;          // rotated source col
            float4 vv = *(const float4*)(sBuf + f * 128 + cs);
            __stcs((float4*)(outb + (size_t)f * HWC + lane * 4), vv);
        }
    }
}

// ===========================================================================
extern "C" void kernel_launch(void* const* d_in, const int* in_sizes, int n_in,
                              void* d_out, int out_size) {
    const float* x = nullptr, *gate_w = nullptr, *gate_b = nullptr, *expert_w = nullptr;
    for (int i = 0; i < n_in; i++) {
        switch (in_sizes[i]) {
            case BB*CC*HH*WW: x        = (const float*)d_in[i]; break;  // 524288
            case EE*CC*3*3:   gate_w   = (const float*)d_in[i]; break;  // 4608
            case EE:          gate_b   = (const float*)d_in[i]; break;  // 8
            case EE*CC*CC:    expert_w = (const float*)d_in[i]; break;  // 32768
            default: break;
        }
    }
    float* out = (float*)d_out;
    const int main_elems = BB * CC * HWC;
    int write_ew = (out_size >= main_elems + BB * EE) ? 1 : 0;

    region_sums_kernel<<<BB * CC, 256>>>(x);
    gate_kernel<<<BB, 256>>>(gate_w, gate_b, out + main_elems, write_ew);
    gemm_kernel<<<dim3(HWC / 128, BB), 256>>>(x, expert_w, out);
}

// round 15
// speedup vs baseline: 1.4173x; 1.1619x over previous
#include <cuda_runtime.h>
#include <cuda_fp16.h>
#include <cstdint>

#define BB 32
#define CC 64
#define HH 64
#define WW 64
#define EE 8
#define HWC (HH*WW)

// Scratch (device globals: no allocation allowed)
__device__ float g_S[BB * 9 * CC];   // box sums [(b*9+k)*64+c], k=di*3+dj
__device__ float g_val[BB];
__device__ int   g_idx[BB];

// ===========================================================================
// helpers
// ===========================================================================
__device__ __forceinline__ uint32_t smem_u32(const void* p) {
    uint32_t a;
    asm("{ .reg .u64 t; cvta.to.shared.u64 t, %1; cvt.u32.u64 %0, t; }" : "=r"(a) : "l"(p));
    return a;
}

__device__ __forceinline__ uint32_t pack_f16x2(float even, float odd) {
    __half2 h = __floats2half2_rn(even, odd);
    return *reinterpret_cast<uint32_t*>(&h);
}

#define LDMATRIX_X4(R, addr) \
    asm volatile("ldmatrix.sync.aligned.m8n8.x4.shared.b16 {%0,%1,%2,%3}, [%4];" \
        : "=r"((R)[0]), "=r"((R)[1]), "=r"((R)[2]), "=r"((R)[3]) : "r"(addr))

#define LDMATRIX_X2T(R, addr) \
    asm volatile("ldmatrix.sync.aligned.m8n8.x2.trans.shared.b16 {%0,%1}, [%2];" \
        : "=r"((R)[0]), "=r"((R)[1]) : "r"(addr))

#define MMA_F16(D, A, B0, B1) \
    asm volatile("mma.sync.aligned.m16n8k16.row.col.f32.f16.f16.f32 " \
        "{%0,%1,%2,%3}, {%4,%5,%6,%7}, {%8,%9}, {%0,%1,%2,%3};" \
        : "+f"((D)[0]), "+f"((D)[1]), "+f"((D)[2]), "+f"((D)[3]) \
        : "r"((A)[0]), "r"((A)[1]), "r"((A)[2]), "r"((A)[3]), "r"(B0), "r"(B1))

// ===========================================================================
// Kernel 1: box sums (proven shape). Block = one (b,c) image; 256 threads.
// ===========================================================================
__global__ __launch_bounds__(256) void region_sums_kernel(const float* __restrict__ x) {
    const int tid = threadIdx.x;
    const float4* base = (const float4*)(x + (size_t)blockIdx.x * HWC);
    float4 v[4];
    #pragma unroll
    for (int i = 0; i < 4; i++) v[i] = base[i * 256 + tid];

    const int g  = tid >> 4;   // 0..15 ; rows touched = i*16 + g
    const int c4 = tid & 15;   // float4 within row

    __shared__ float sRow[4][16];  // partial sums of edge rows 0,1,62,63
    __shared__ float sRE[4][4];    // edge row elems: x[r][0],[1],[62],[63]
    __shared__ float sCol[4][16];  // per-g partials of cols 0,1,62,63
    __shared__ float sG[8];        // per-warp grand totals

    float ps[4], gsum = 0.f;
    #pragma unroll
    for (int i = 0; i < 4; i++) {
        ps[i] = (v[i].x + v[i].y) + (v[i].z + v[i].w);
        gsum += ps[i];
    }
    if (g == 0)  sRow[0][c4] = ps[0];
    if (g == 1)  sRow[1][c4] = ps[0];
    if (g == 14) sRow[2][c4] = ps[3];
    if (g == 15) sRow[3][c4] = ps[3];
    if (c4 == 0) {
        sCol[0][g] = (v[0].x + v[1].x) + (v[2].x + v[3].x);
        sCol[1][g] = (v[0].y + v[1].y) + (v[2].y + v[3].y);
        if (g == 0)  { sRE[0][0] = v[0].x; sRE[0][1] = v[0].y; }
        if (g == 1)  { sRE[1][0] = v[0].x; sRE[1][1] = v[0].y; }
        if (g == 14) { sRE[2][0] = v[3].x; sRE[2][1] = v[3].y; }
        if (g == 15) { sRE[3][0] = v[3].x; sRE[3][1] = v[3].y; }
    }
    if (c4 == 15) {
        sCol[2][g] = (v[0].z + v[1].z) + (v[2].z + v[3].z);
        sCol[3][g] = (v[0].w + v[1].w) + (v[2].w + v[3].w);
        if (g == 0)  { sRE[0][2] = v[0].z; sRE[0][3] = v[0].w; }
        if (g == 1)  { sRE[1][2] = v[0].z; sRE[1][3] = v[0].w; }
        if (g == 14) { sRE[2][2] = v[3].z; sRE[2][3] = v[3].w; }
        if (g == 15) { sRE[3][2] = v[3].z; sRE[3][3] = v[3].w; }
    }
    #pragma unroll
    for (int o = 16; o; o >>= 1) gsum += __shfl_xor_sync(0xffffffffu, gsum, o);
    if ((tid & 31) == 0) sG[tid >> 5] = gsum;
    __syncthreads();

    if (tid < 9) {
        int di = tid / 3, dj = tid - di * 3;
        float G = 0.f;
        #pragma unroll
        for (int j = 0; j < 8; j++) G += sG[j];
        float c0 = 0.f, c1 = 0.f, c62 = 0.f, c63 = 0.f;
        #pragma unroll
        for (int j = 0; j < 16; j++) {
            c0 += sCol[0][j]; c1 += sCol[1][j]; c62 += sCol[2][j]; c63 += sCol[3][j];
        }
        float colc = (dj == 0) ? (c62 + c63) : (dj == 1) ? (c0 + c63) : (c0 + c1);
        float T = G - colc;                 // sum of cv_dj over all 64 rows
        float rw[4];
        #pragma unroll
        for (int er = 0; er < 4; er++) {
            float s = 0.f;
            #pragma unroll
            for (int j = 0; j < 16; j++) s += sRow[er][j];
            float ec = (dj == 0) ? (sRE[er][2] + sRE[er][3])
                     : (dj == 1) ? (sRE[er][0] + sRE[er][3])
                                 : (sRE[er][0] + sRE[er][1]);
            rw[er] = s - ec;                // cv_dj of that edge row
        }
        float sub = (di == 0) ? (rw[2] + rw[3])
                  : (di == 1) ? (rw[0] + rw[3])
                              : (rw[0] + rw[1]);
        int b = blockIdx.x >> 6, c = blockIdx.x & 63;
        g_S[(b * 9 + tid) * CC + c] = T - sub;
    }
}

// ===========================================================================
// Kernel 2: gate (32 blocks; smem-staged g_S).
// ===========================================================================
__global__ __launch_bounds__(256) void gate_kernel(const float* __restrict__ gate_w,
                                                   const float* __restrict__ gate_b,
                                                   float* __restrict__ ew_out,
                                                   int write_ew) {
    int b = blockIdx.x;
    int tid = threadIdx.x;
    __shared__ float Ssh[9 * 64];
    __shared__ float gat[8];

    for (int i = tid; i < 576; i += 256) Ssh[i] = g_S[b*576 + i];
    __syncthreads();

    int warp = tid >> 5, lane = tid & 31;  // warp = expert
    float acc = 0.f;
    for (int idx = lane; idx < 576; idx += 32) {
        int c = idx / 9;
        int k = idx - c * 9;
        acc += gate_w[warp * 576 + idx] * Ssh[k * 64 + c];
    }
    #pragma unroll
    for (int o = 16; o; o >>= 1) acc += __shfl_down_sync(0xffffffffu, acc, o);
    if (lane == 0) gat[warp] = acc + gate_b[warp] * 3844.0f;  // 62*62 positions
    __syncthreads();

    if (tid == 0) {
        float m = gat[0]; int mi = 0;
        #pragma unroll
        for (int e = 1; e < 8; e++) { if (gat[e] > m) { m = gat[e]; mi = e; } }
        float s = 0.f;
        #pragma unroll
        for (int e = 0; e < 8; e++) s += expf(gat[e] - m);
        g_val[b] = 1.0f / s;
        g_idx[b] = mi;
    }
    __syncthreads();
    if (write_ew && tid < 8) {
        ew_out[b * 8 + tid] = (tid == g_idx[b]) ? g_val[b] : 0.0f;
    }
}

// ===========================================================================
// Kernel 3: fp16 mma.sync GEMM — W staged in smem, fragments via ldmatrix.
//   W load: 4x coalesced LDG.128/thread -> fp16 tile, pitch 36 words
//           (rows shift 4 banks -> conflict-free ldmatrix.x4).
//   A frags: 4 x ldmatrix.x4 per warp (was 16 scattered LDG.64/thread).
//   X: fp16 smem tile, ldmatrix.x2.trans. Epilogue: direct __stcs.
// Block 256 thr (8 warps: wf=warp>>1 16f, wn=warp&1 64hw); tile 64f x 128hw.
// ===========================================================================
#define WPITCH 36u   // words per W row (32 data words + 4 pad) -> 144B row pitch
#define XPITCH 68u   // words per X row (64 data words + 4 pad)

__global__ __launch_bounds__(256) void gemm_kernel(const float* __restrict__ x,
                                                   const float* __restrict__ expert_w,
                                                   float* __restrict__ out) {
    __shared__ uint32_t sW[64 * WPITCH];   // 9.2 KB fp16x2 W tile [f][c-pairs]
    __shared__ uint32_t sX[64 * XPITCH];   // 17.4 KB fp16x2 X tile [c][hw-pairs]
    __shared__ float shv;
    __shared__ int   she;

    const int tid   = threadIdx.x;
    const int warp  = tid >> 5, lane = tid & 31;
    const int chunk = blockIdx.x;
    const int b     = blockIdx.y;
    const int hw0   = chunk * 128;

    if (tid == 0) { shv = g_val[b]; she = g_idx[b]; }
    __syncthreads();
    const int e = she;

    // ---- stage W: coalesced gmem read (L2-hot 16KB), fp16 convert ----
    {
        const float4* Wb4 = (const float4*)(expert_w + (size_t)e * 4096);
        #pragma unroll
        for (int i = 0; i < 4; i++) {
            int p = tid + i * 256;          // float4 index 0..1023
            int f = p >> 4, q = p & 15;     // 16 float4 per 64-float row
            float4 w = Wb4[p];
            sW[f * WPITCH + q * 2]     = pack_f16x2(w.x, w.y);
            sW[f * WPITCH + q * 2 + 1] = pack_f16x2(w.z, w.w);
        }
    }

    // ---- stage X: fp32 (L2-hot after kernel 1) -> fp16 smem ----
    const float* Xsrc = x + (size_t)b * CC * HWC + hw0;
    {
        float4 xv[8];
        #pragma unroll
        for (int i = 0; i < 8; i++) {
            int p = tid + i * 256;          // float4 index 0..2047
            int c = p >> 5, q = p & 31;
            xv[i] = *(const float4*)(Xsrc + (size_t)c * HWC + q * 4);
        }
        #pragma unroll
        for (int i = 0; i < 8; i++) {
            int p = tid + i * 256;
            int c = p >> 5, q = p & 31;
            uint2 w;
            w.x = pack_f16x2(xv[i].x, xv[i].y);
            w.y = pack_f16x2(xv[i].z, xv[i].w);
            *(uint2*)(sX + c * XPITCH + q * 2) = w;
        }
    }
    __syncthreads();
    const float val = shv;

    // ---- A fragments via ldmatrix.x4 (R4-verified layout) ----
    const int wf = warp >> 1;   // 0..3 : 16 f rows each
    const int wn = warp & 1;    // 0..1 : 64 hw cols each
    const uint32_t swb = smem_u32(sW);
    uint32_t af[4][4];
    {
        uint32_t rowsel = (uint32_t)(lane & 15);
        uint32_t seg    = (uint32_t)(lane >> 4) * 16u;   // k +8 halves
        uint32_t row    = (uint32_t)(wf * 16) + rowsel;
        #pragma unroll
        for (int kt = 0; kt < 4; kt++) {
            uint32_t off = row * (WPITCH * 4u) + (uint32_t)kt * 32u + seg;
            LDMATRIX_X4(af[kt], swb + off);
        }
    }

    float acc[8][4];
    #pragma unroll
    for (int nt = 0; nt < 8; nt++)
        #pragma unroll
        for (int q = 0; q < 4; q++) acc[nt][q] = 0.f;

    const uint32_t sxb = smem_u32(sX);
    const uint32_t krow = (uint32_t)(lane & 15);
    #pragma unroll
    for (int kt = 0; kt < 4; kt++) {
        uint32_t kbase = ((uint32_t)(kt * 16) + krow) * (XPITCH * 4u);
        #pragma unroll
        for (int nt = 0; nt < 8; nt++) {
            uint32_t noff = (uint32_t)(wn * 64 + nt * 8) * 2u;
            uint32_t bf[2];
            LDMATRIX_X2T(bf, sxb + kbase + noff);
            MMA_F16(acc[nt], af[kt], bf[0], bf[1]);
        }
    }

    // ---- epilogue: streaming stores ----
    float* outb = out + (size_t)b * CC * HWC + hw0;
    int f0 = wf * 16 + (lane >> 2);
    int cbase = wn * 64 + (lane & 3) * 2;
    #pragma unroll
    for (int nt = 0; nt < 8; nt++) {
        int cc = cbase + nt * 8;
        float2 v0 = make_float2(acc[nt][0] * val, acc[nt][1] * val);
        float2 v1 = make_float2(acc[nt][2] * val, acc[nt][3] * val);
        __stcs((float2*)(outb + (size_t)f0 * HWC + cc),       v0);
        __stcs((float2*)(outb + (size_t)(f0 + 8) * HWC + cc), v1);
    }
}

// ===========================================================================
extern "C" void kernel_launch(void* const* d_in, const int* in_sizes, int n_in,
                              void* d_out, int out_size) {
    const float* x = nullptr, *gate_w = nullptr, *gate_b = nullptr, *expert_w = nullptr;
    for (int i = 0; i < n_in; i++) {
        switch (in_sizes[i]) {
            case BB*CC*HH*WW: x        = (const float*)d_in[i]; break;  // 524288
            case EE*CC*3*3:   gate_w   = (const float*)d_in[i]; break;  // 4608
            case EE:          gate_b   = (const float*)d_in[i]; break;  // 8
            case EE*CC*CC:    expert_w = (const float*)d_in[i]; break;  // 32768
            default: break;
        }
    }
    float* out = (float*)d_out;
    const int main_elems = BB * CC * HWC;
    int write_ew = (out_size >= main_elems + BB * EE) ? 1 : 0;

    region_sums_kernel<<<BB * CC, 256>>>(x);
    gate_kernel<<<BB, 256>>>(gate_w, gate_b, out + main_elems, write_ew);
    gemm_kernel<<<dim3(HWC / 128, BB), 256>>>(x, expert_w, out);
}